// round 17
// baseline (speedup 1.0000x reference)
#include <cuda_runtime.h>
#include <cuda_fp16.h>
#include <cstdint>

// Problem constants
#define BATCH 4
#define SEQ   2048
#define EMB   1024
#define NH    16
#define DH    64
#define ROWS  (BATCH * SEQ)        // 8192
#define QKVN  (3 * EMB)            // 3072

// Scratch (allocation-guard-safe device globals), fp16 datapath
__device__ __half g_xh [(size_t)ROWS * EMB];    // x, fp16            16 MB
__device__ __half g_wqT[(size_t)QKVN * EMB];    // w_qkv^T [3072][1024] 6 MB
__device__ __half g_woT[(size_t)EMB * EMB];     // w_out^T [1024][1024] 2 MB
__device__ __half g_qkv[(size_t)ROWS * QKVN];   // qkv, fp16           48 MB
__device__ __half g_att[(size_t)ROWS * EMB];    // attention out, fp16 16 MB

// ---------------------------------------------------------------------------
// Helpers
// ---------------------------------------------------------------------------
__device__ __forceinline__ float ex2(float x) {
    float r;
    asm("ex2.approx.f32 %0, %1;" : "=f"(r) : "f"(x));
    return r;
}

__device__ __forceinline__ unsigned h2ex2(unsigned x) {
    unsigned r;
    asm("ex2.approx.f16x2 %0, %1;" : "=r"(r) : "r"(x));
    return r;
}

__device__ __forceinline__ unsigned smem_u32(const void* p) {
    return (unsigned)__cvta_generic_to_shared(p);
}

__device__ __forceinline__ void cp16(unsigned dst, const void* src) {
    asm volatile("cp.async.cg.shared.global [%0], [%1], 16;"
                 :: "r"(dst), "l"(__cvta_generic_to_global(src)));
}
#define CP_COMMIT() asm volatile("cp.async.commit_group;" ::: "memory")
#define CP_WAIT(n)  asm volatile("cp.async.wait_group %0;" :: "n"(n) : "memory")

// fp16 m16n8k16: D(f32) += A(f16) @ B(f16). NOT volatile (pure, reorderable).
__device__ __forceinline__ void mma_f16(float d[4], const unsigned a[4],
                                        unsigned b0, unsigned b1) {
    asm("mma.sync.aligned.m16n8k16.row.col.f32.f16.f16.f32 "
        "{%0,%1,%2,%3}, {%4,%5,%6,%7}, {%8,%9}, {%0,%1,%2,%3};\n"
        : "+f"(d[0]), "+f"(d[1]), "+f"(d[2]), "+f"(d[3])
        : "r"(a[0]), "r"(a[1]), "r"(a[2]), "r"(a[3]), "r"(b0), "r"(b1));
}

// ldmatrix x4 (non-transposed)
__device__ __forceinline__ void ldsm_x4(unsigned& r0, unsigned& r1,
                                        unsigned& r2, unsigned& r3,
                                        unsigned addr) {
    asm("ldmatrix.sync.aligned.m8n8.x4.shared.b16 {%0,%1,%2,%3}, [%4];"
        : "=r"(r0), "=r"(r1), "=r"(r2), "=r"(r3) : "r"(addr));
}

// ldmatrix x4 transposed (for V consumed as V^T without a transpose pass)
__device__ __forceinline__ void ldsm_x4_t(unsigned& r0, unsigned& r1,
                                          unsigned& r2, unsigned& r3,
                                          unsigned addr) {
    asm("ldmatrix.sync.aligned.m8n8.x4.trans.shared.b16 {%0,%1,%2,%3}, [%4];"
        : "=r"(r0), "=r"(r1), "=r"(r2), "=r"(r3) : "r"(addr));
}

__device__ __forceinline__ unsigned pack_h2(float lo, float hi) {
    __half2 h = __floats2half2_rn(lo, hi);
    return *reinterpret_cast<unsigned*>(&h);
}

// ---------------------------------------------------------------------------
// Prep kernels
// ---------------------------------------------------------------------------
__global__ __launch_bounds__(256)
void cvt_h_kernel(const float* __restrict__ in, __half* __restrict__ out) {
    size_t i = ((size_t)blockIdx.x * 256 + threadIdx.x) * 8;
    float4 v0 = *(const float4*)(in + i);
    float4 v1 = *(const float4*)(in + i + 4);
    uint4 o;
    o.x = pack_h2(v0.x, v0.y); o.y = pack_h2(v0.z, v0.w);
    o.z = pack_h2(v1.x, v1.y); o.w = pack_h2(v1.z, v1.w);
    *(uint4*)(out + i) = o;
}

__global__ __launch_bounds__(256)
void transpose_h_kernel(const float* __restrict__ in, __half* __restrict__ out,
                        int R, int C) {
    __shared__ float tile[32][33];
    const int tx = threadIdx.x, ty = threadIdx.y;
    const int c0 = blockIdx.x * 32, r0 = blockIdx.y * 32;
    #pragma unroll
    for (int i = 0; i < 4; i++)
        tile[ty + i * 8][tx] = in[(size_t)(r0 + ty + i * 8) * C + c0 + tx];
    __syncthreads();
    #pragma unroll
    for (int i = 0; i < 4; i++)
        out[(size_t)(c0 + ty + i * 8) * R + r0 + tx] =
            __float2half_rn(tile[tx][ty + i * 8]);
}

// ---------------------------------------------------------------------------
// fp16 GEMM: C[M,N] = A[M,K] @ Bt[N,K]^T. A, Bt fp16 k-major. BK=64.
// Block tile 128x128, 3-stage cp.async, 256 threads = 8 warps (2x4),
// warp tile 64x32, m16n8k16, ldmatrix.x4. 2 CTAs/SM -> 4 warps/SMSP.
// ---------------------------------------------------------------------------
#define H_ROWB 144                         // bytes per smem row
#define G_TILEB (128 * H_ROWB)             // 18432 B (A or Bt tile)
#define G_STAGE (2 * G_TILEB)              // 36864 B
#define G_STAGES 3
#define GEMM_SMEM_BYTES (G_STAGES * G_STAGE)   // 110592 B

template<bool HALF_OUT>
__global__ __launch_bounds__(256, 2)
void gemm_f16_kernel(const __half* __restrict__ A, const __half* __restrict__ Bt,
                     void* __restrict__ Cv, int N, int K) {
    extern __shared__ char smc[];
    const unsigned abase0 = smem_u32(smc);
    const unsigned bbase0 = abase0 + G_TILEB;

    const int tid  = threadIdx.x;
    const int lane = tid & 31;
    const int wid  = tid >> 5;
    const int gi   = lane >> 2;
    const int ti   = lane & 3;
    const int warp_m = wid >> 2;    // 0..1
    const int warp_n = wid & 3;     // 0..3
    const int m0 = blockIdx.y * 128;
    const int n0 = blockIdx.x * 128;

    const int arow = lane & 15;
    const int ahi  = (lane >> 4) << 4;
    const int brow = (lane & 7) + ((lane >> 4) << 3);
    const int bhi  = ((lane >> 3) & 1) << 4;

    auto stage = [&](int t, int buf) {
        const unsigned ab = abase0 + buf * G_STAGE;
        const unsigned bb = bbase0 + buf * G_STAGE;
        const __half* Ag = A  + (size_t)m0 * K + t * 64;
        const __half* Bg = Bt + (size_t)n0 * K + t * 64;
        #pragma unroll
        for (int i = 0; i < 4; i++) {          // 1024 16B chunks each
            int idx = tid + i * 256;
            int r = idx >> 3, c = idx & 7;     // 128 rows x 8 chunks
            cp16(ab + r * H_ROWB + c * 16, Ag + (size_t)r * K + c * 8);
            cp16(bb + r * H_ROWB + c * 16, Bg + (size_t)r * K + c * 8);
        }
    };

    float acc[4][4][4];
    #pragma unroll
    for (int i = 0; i < 4; i++)
        #pragma unroll
        for (int j = 0; j < 4; j++)
            acc[i][j][0] = acc[i][j][1] = acc[i][j][2] = acc[i][j][3] = 0.0f;

    const int KT = K >> 6;                     // 16 k-tiles
    stage(0, 0); CP_COMMIT();
    stage(1, 1); CP_COMMIT();

    for (int t = 0; t < KT; t++) {
        const int buf = t % G_STAGES;
        if (t + 1 < KT) { CP_WAIT(1); } else { CP_WAIT(0); }
        __syncthreads();
        if (t + 2 < KT) { stage(t + 2, (t + 2) % G_STAGES); CP_COMMIT(); }

        const unsigned As_addr = abase0 + buf * G_STAGE;
        const unsigned Bs_addr = bbase0 + buf * G_STAGE;
        #pragma unroll
        for (int s = 0; s < 4; s++) {          // 4 x k16 steps
            unsigned af[4][4];
            unsigned bf[4][2];
            #pragma unroll
            for (int mi = 0; mi < 4; mi++)
                ldsm_x4(af[mi][0], af[mi][1], af[mi][2], af[mi][3],
                        As_addr + (warp_m * 64 + mi * 16 + arow) * H_ROWB
                                + s * 32 + ahi);
            #pragma unroll
            for (int njp = 0; njp < 2; njp++)
                ldsm_x4(bf[2 * njp][0], bf[2 * njp][1],
                        bf[2 * njp + 1][0], bf[2 * njp + 1][1],
                        Bs_addr + (warp_n * 32 + njp * 16 + brow) * H_ROWB
                                + s * 32 + bhi);
            #pragma unroll
            for (int mi = 0; mi < 4; mi++)
                #pragma unroll
                for (int nj = 0; nj < 4; nj++)
                    mma_f16(acc[mi][nj], af[mi], bf[nj][0], bf[nj][1]);
        }
    }

    #pragma unroll
    for (int mi = 0; mi < 4; mi++) {
        const int row = m0 + warp_m * 64 + mi * 16 + gi;
        #pragma unroll
        for (int nj = 0; nj < 4; nj++) {
            const int col = n0 + warp_n * 32 + nj * 8 + 2 * ti;
            if (HALF_OUT) {
                __half* C = (__half*)Cv;
                *(unsigned*)&C[(size_t)row * N + col] =
                    pack_h2(acc[mi][nj][0], acc[mi][nj][1]);
                *(unsigned*)&C[(size_t)(row + 8) * N + col] =
                    pack_h2(acc[mi][nj][2], acc[mi][nj][3]);
            } else {
                float* C = (float*)Cv;
                *(float2*)&C[(size_t)row * N + col] =
                    make_float2(acc[mi][nj][0], acc[mi][nj][1]);
                *(float2*)&C[(size_t)(row + 8) * N + col] =
                    make_float2(acc[mi][nj][2], acc[mi][nj][3]);
            }
        }
    }
}

// ---------------------------------------------------------------------------
// Flash attention, fp16 m16n8k16 + ldmatrix. Br=128, Bc=64, 128 threads =
// 4 warps, warp owns 32 query rows. V consumed straight from g_qkv (rows=t,
// d contiguous) via ldmatrix.trans — no V-transpose pass. P in registers;
// exp2 on f16x2 MUFU; row-sum l via ones-column mma.
//   smem: K0..K2, V0..V2 (64x144B each) + Q (128x144B) = 73728 B
// ---------------------------------------------------------------------------
#define H_ROWW 36
#define KV_TILEB (64 * H_ROWB)             // 9216 B
#define AQ_OFF   (6 * KV_TILEB)
#define ATTN_SMEM_BYTES (6 * KV_TILEB + 128 * H_ROWB)   // 73728 B
#define QSCALE  (0.125f * 1.4426950408889634f)          // log2e / sqrt(dh)

__global__ __launch_bounds__(128, 2)
void flash_attn_f16_kernel() {
    extern __shared__ char smc[];
    const unsigned smb = smem_u32(smc);

    const int tid  = threadIdx.x;
    const int lane = tid & 31;
    const int wid  = tid >> 5;          // 0..3
    const int gi   = lane >> 2;
    const int ti   = lane & 3;
    const int bh = blockIdx.y;
    const int b = bh >> 4, h = bh & 15;
    const int qb = blockIdx.x;          // 128-row query tile

    const __half* qbase = g_qkv + (size_t)(b * SEQ + qb * 128) * QKVN + h * DH;
    const __half* kbase = g_qkv + (size_t)(b * SEQ) * QKVN + EMB + h * DH;
    const __half* vbase = g_qkv + (size_t)(b * SEQ) * QKVN + 2 * EMB + h * DH;

    // K b-fragment addressing (non-trans; K tile rows = t, k=d contiguous)
    const int brow = (lane & 7) + ((lane >> 4) << 3);
    const int bhi  = ((lane >> 3) & 1) << 4;
    // V b-fragment addressing (trans; V tile rows = t = k, n=d contiguous)
    //   m0: k rows 0-7, n-lo | m1: k rows 8-15, n-lo | m2/m3: same, n-hi(+16B)
    const int vrow = (lane & 7) + (((lane >> 3) & 1) << 3);
    const int vcol = (lane >> 4) << 4;

    // Ones-column b-fragment: B[t][0]=1 -> lanes with n-col gi==0
    const unsigned bones = (gi == 0) ? 0x3C003C00u : 0u;

    auto stage_kv = [&](int jt, int buf) {
        const unsigned kb = smb + buf * KV_TILEB;
        const unsigned vb = smb + (3 + buf) * KV_TILEB;
        #pragma unroll
        for (int i = 0; i < 4; i++) {
            int idx = tid + i * 128;    // 0..511
            int r = idx >> 3, c = idx & 7;
            size_t g = (size_t)(jt * 64 + r) * QKVN + c * 8;
            cp16(kb + r * H_ROWB + c * 16, kbase + g);
            cp16(vb + r * H_ROWB + c * 16, vbase + g);
        }
    };

    // Prologue: group0 = {KV tile 0, Q}; group1 = {KV tile 1}
    stage_kv(0, 0);
    {
        const unsigned qsm = smb + AQ_OFF;
        #pragma unroll
        for (int i = 0; i < 8; i++) {
            int idx = tid + i * 128;
            int r = idx >> 3, c = idx & 7;
            cp16(qsm + r * H_ROWB + c * 16, qbase + (size_t)r * QKVN + c * 8);
        }
    }
    CP_COMMIT();
    stage_kv(1, 1);
    CP_COMMIT();

    CP_WAIT(1);
    __syncthreads();

    // Q a-fragments (one-time scalar loads)
    const unsigned* Qw = (const unsigned*)(smc + AQ_OFF);
    unsigned qa[2][4][4];
    #pragma unroll
    for (int kc = 0; kc < 4; kc++) {
        #pragma unroll
        for (int hh = 0; hh < 2; hh++) {
            const int r = wid * 32 + hh * 16 + gi;
            const int w = kc * 8 + ti;
            qa[hh][kc][0] = Qw[r * H_ROWW + w];
            qa[hh][kc][1] = Qw[(r + 8) * H_ROWW + w];
            qa[hh][kc][2] = Qw[r * H_ROWW + w + 4];
            qa[hh][kc][3] = Qw[(r + 8) * H_ROWW + w + 4];
        }
    }

    float o[2][8][4];
    float osum[2][4];
    #pragma unroll
    for (int hh = 0; hh < 2; hh++) {
        #pragma unroll
        for (int j = 0; j < 8; j++)
            o[hh][j][0] = o[hh][j][1] = o[hh][j][2] = o[hh][j][3] = 0.0f;
        osum[hh][0] = osum[hh][1] = osum[hh][2] = osum[hh][3] = 0.0f;
    }
    float mrow[2][2] = {{-1e30f, -1e30f}, {-1e30f, -1e30f}};

    const int NT = SEQ / 64;
    for (int jt = 0; jt < NT; jt++) {
        const int buf = jt % 3;
        if (jt + 1 < NT) { CP_WAIT(1); } else { CP_WAIT(0); }
        __syncthreads();
        if (jt + 2 < NT) { stage_kv(jt + 2, (jt + 2) % 3); CP_COMMIT(); }

        const unsigned Ks_addr = smb + buf * KV_TILEB;
        const unsigned Vs_addr = smb + (3 + buf) * KV_TILEB;

        // ---- S = Q @ K^T
        float s[2][8][4];
        #pragma unroll
        for (int hh = 0; hh < 2; hh++)
            #pragma unroll
            for (int j = 0; j < 8; j++)
                s[hh][j][0] = s[hh][j][1] = s[hh][j][2] = s[hh][j][3] = 0.0f;
        #pragma unroll
        for (int kc = 0; kc < 4; kc++) {
            unsigned bf[8][2];
            #pragma unroll
            for (int jp = 0; jp < 4; jp++)
                ldsm_x4(bf[2 * jp][0], bf[2 * jp][1],
                        bf[2 * jp + 1][0], bf[2 * jp + 1][1],
                        Ks_addr + (jp * 16 + brow) * H_ROWB + kc * 32 + bhi);
            #pragma unroll
            for (int j = 0; j < 8; j++) {
                mma_f16(s[0][j], qa[0][kc], bf[j][0], bf[j][1]);
                mma_f16(s[1][j], qa[1][kc], bf[j][0], bf[j][1]);
            }
        }

        // ---- Online softmax (base-2). P computed directly in f16x2.
        unsigned pa[2][4][4];     // P packed as PV A-fragments
        #pragma unroll
        for (int hh = 0; hh < 2; hh++) {
            float a0 = -1e30f, a1 = -1e30f;
            #pragma unroll
            for (int j = 0; j < 8; j++) {
                a0 = fmaxf(a0, fmaxf(s[hh][j][0], s[hh][j][1]));
                a1 = fmaxf(a1, fmaxf(s[hh][j][2], s[hh][j][3]));
            }
            a0 = fmaxf(a0, __shfl_xor_sync(0xffffffffu, a0, 1));
            a0 = fmaxf(a0, __shfl_xor_sync(0xffffffffu, a0, 2));
            a1 = fmaxf(a1, __shfl_xor_sync(0xffffffffu, a1, 1));
            a1 = fmaxf(a1, __shfl_xor_sync(0xffffffffu, a1, 2));

            float mn0 = fmaxf(mrow[hh][0], a0), mn1 = fmaxf(mrow[hh][1], a1);
            float c0 = ex2((mrow[hh][0] - mn0) * QSCALE);
            float c1 = ex2((mrow[hh][1] - mn1) * QSCALE);
            float z0 = mn0 * QSCALE, z1 = mn1 * QSCALE;
            mrow[hh][0] = mn0; mrow[hh][1] = mn1;

            #pragma unroll
            for (int j = 0; j < 8; j++) {
                o[hh][j][0] *= c0; o[hh][j][1] *= c0;
                o[hh][j][2] *= c1; o[hh][j][3] *= c1;
            }
            osum[hh][0] *= c0; osum[hh][1] *= c0;
            osum[hh][2] *= c1; osum[hh][3] *= c1;

            #pragma unroll
            for (int j = 0; j < 8; j++) {
                float y0 = fmaf(s[hh][j][0], QSCALE, -z0);
                float y1 = fmaf(s[hh][j][1], QSCALE, -z0);
                float y2 = fmaf(s[hh][j][2], QSCALE, -z1);
                float y3 = fmaf(s[hh][j][3], QSCALE, -z1);
                unsigned ph0 = h2ex2(pack_h2(y0, y1));
                unsigned ph1 = h2ex2(pack_h2(y2, y3));
                const int kc = j >> 1;
                const int pos = (j & 1) << 1;
                pa[hh][kc][pos]     = ph0;
                pa[hh][kc][pos + 1] = ph1;
            }
        }

        // ---- O += P @ V ; osum += P @ ones  (V b-frags via trans ldmatrix)
        #pragma unroll
        for (int kc = 0; kc < 4; kc++) {
            unsigned bf[8][2];
            #pragma unroll
            for (int jp = 0; jp < 4; jp++)
                ldsm_x4_t(bf[2 * jp][0], bf[2 * jp][1],
                          bf[2 * jp + 1][0], bf[2 * jp + 1][1],
                          Vs_addr + (kc * 16 + vrow) * H_ROWB + jp * 32 + vcol);
            #pragma unroll
            for (int j = 0; j < 8; j++) {
                mma_f16(o[0][j], pa[0][kc], bf[j][0], bf[j][1]);
                mma_f16(o[1][j], pa[1][kc], bf[j][0], bf[j][1]);
            }
            mma_f16(osum[0], pa[0][kc], bones, bones);
            mma_f16(osum[1], pa[1][kc], bones, bones);
        }
    }

    // ---- Epilogue: l from the ones-column (quad leader holds col 0)
    #pragma unroll
    for (int hh = 0; hh < 2; hh++) {
        const int qlead = lane & 28;
        const float l0 = __shfl_sync(0xffffffffu, osum[hh][0], qlead);
        const float l1 = __shfl_sync(0xffffffffu, osum[hh][2], qlead);
        const float inv0 = 1.0f / l0;
        const float inv1 = 1.0f / l1;
        const size_t row0 = (size_t)(b * SEQ + qb * 128 + wid * 32 + hh * 16 + gi);
        const size_t row1 = row0 + 8;
        #pragma unroll
        for (int j = 0; j < 8; j++) {
            size_t col = h * DH + j * 8 + 2 * ti;
            *(unsigned*)&g_att[row0 * EMB + col] =
                pack_h2(o[hh][j][0] * inv0, o[hh][j][1] * inv0);
            *(unsigned*)&g_att[row1 * EMB + col] =
                pack_h2(o[hh][j][2] * inv1, o[hh][j][3] * inv1);
        }
    }
}

// ---------------------------------------------------------------------------
// Launch
// ---------------------------------------------------------------------------
extern "C" void kernel_launch(void* const* d_in, const int* in_sizes, int n_in,
                              void* d_out, int out_size) {
    const float* x     = (const float*)d_in[0];   // [4,2048,1024]
    const float* w_qkv = (const float*)d_in[1];   // [1024,3072]
    const float* w_out = (const float*)d_in[2];   // [1024,1024]
    float* out = (float*)d_out;                   // [4,2048,1024]

    __half *xh, *wqT, *woT, *qkv, *att;
    cudaGetSymbolAddress((void**)&xh,  g_xh);
    cudaGetSymbolAddress((void**)&wqT, g_wqT);
    cudaGetSymbolAddress((void**)&woT, g_woT);
    cudaGetSymbolAddress((void**)&qkv, g_qkv);
    cudaGetSymbolAddress((void**)&att, g_att);

    cudaFuncSetAttribute(gemm_f16_kernel<true>,
                         cudaFuncAttributeMaxDynamicSharedMemorySize, GEMM_SMEM_BYTES);
    cudaFuncSetAttribute(gemm_f16_kernel<false>,
                         cudaFuncAttributeMaxDynamicSharedMemorySize, GEMM_SMEM_BYTES);
    cudaFuncSetAttribute(flash_attn_f16_kernel,
                         cudaFuncAttributeMaxDynamicSharedMemorySize, ATTN_SMEM_BYTES);

    // 0) Convert / transpose inputs to fp16
    cvt_h_kernel<<<(ROWS * EMB) / (256 * 8), 256>>>(x, xh);
    {
        dim3 g(QKVN / 32, EMB / 32);
        transpose_h_kernel<<<g, dim3(32, 8)>>>(w_qkv, wqT, EMB, QKVN);
    }
    {
        dim3 g(EMB / 32, EMB / 32);
        transpose_h_kernel<<<g, dim3(32, 8)>>>(w_out, woT, EMB, EMB);
    }

    // 1) QKV projection -> g_qkv (fp16)
    {
        dim3 grid(QKVN / 128, ROWS / 128);
        gemm_f16_kernel<true><<<grid, 256, GEMM_SMEM_BYTES>>>(xh, wqT, qkv, QKVN, EMB);
    }
    // 2) Flash attention -> g_att (fp16); V read directly from g_qkv
    {
        dim3 grid(SEQ / 128, BATCH * NH);
        flash_attn_f16_kernel<<<grid, 128, ATTN_SMEM_BYTES>>>();
    }
    // 3) Output projection -> d_out (fp32)
    {
        dim3 grid(EMB / 128, ROWS / 128);
        gemm_f16_kernel<false><<<grid, 256, GEMM_SMEM_BYTES>>>(att, woT, out, EMB, EMB);
    }
}